// round 3
// baseline (speedup 1.0000x reference)
#include <cuda_runtime.h>
#include <math.h>
#include <math_constants.h>

#define N_TOK 4096
#define DMODEL 256
#define NHEAD 4
#define DHEAD 64
#define TOPK 30
#define SCALE 0.25f
#define LN_EPS 1e-5f

typedef unsigned long long ull;

// ---------------- scratch ----------------------------------------------------------
__device__ float g_q[N_TOK * DMODEL];
__device__ float g_k[N_TOK * DMODEL];
__device__ float g_v[N_TOK * DMODEL];
__device__ float g_ctx[N_TOK * DMODEL];
__device__ float g_resid[N_TOK * DMODEL];

// ---------------- helpers -----------------------------------------------------------
__device__ __forceinline__ void fma2(ull& d, ull a, ull b) {
    asm("fma.rn.f32x2 %0, %1, %2, %0;" : "+l"(d) : "l"(a), "l"(b));
}
__device__ __forceinline__ float2 unpack2(ull v) {
    float2 f;
    asm("mov.b64 {%0, %1}, %2;" : "=f"(f.x), "=f"(f.y) : "l"(v));
    return f;
}
__device__ __forceinline__ unsigned ford(float f) {  // monotone float->uint
    unsigned u = __float_as_uint(f);
    return (u & 0x80000000u) ? ~u : (u | 0x80000000u);
}
__device__ __forceinline__ float unford(unsigned u) {
    return __uint_as_float((u & 0x80000000u) ? (u & 0x7FFFFFFFu) : ~u);
}

// ---------------- 128x64-tile fp32 GEMM: C = A @ B^T (+bias)(+res) ------------------
template <bool ADD_RES>
__device__ __forceinline__ void gemm128_body(const float* __restrict__ A,
                                             const float* __restrict__ B,
                                             const float* __restrict__ bias,
                                             const float* __restrict__ res,
                                             float* __restrict__ C) {
    __shared__ ull As[128 * 32];
    __shared__ ull Bs[64 * 32];
    const int tid = threadIdx.x;
    const int bm = blockIdx.y * 128;
    const int bn = blockIdx.x * 64;
    const int qg = tid >> 4;  // 0..15, 8 rows each
    const int kg = tid & 15;  // 0..15, 4 cols each

    ull acc[8][4];
#pragma unroll
    for (int a = 0; a < 8; ++a)
#pragma unroll
        for (int b = 0; b < 4; ++b) acc[a][b] = 0ull;

    for (int kk = 0; kk < 256; kk += 64) {
        __syncthreads();
#pragma unroll
        for (int i = 0; i < 16; ++i) {
            int idx = tid + i * 256;
            int r = idx >> 5, c = idx & 31;
            As[(r << 5) | (c ^ (r >> 3))] =
                *(const ull*)(A + (size_t)(bm + r) * 256 + kk + c * 2);
        }
#pragma unroll
        for (int i = 0; i < 8; ++i) {
            int idx = tid + i * 256;
            int r = idx >> 5, c = idx & 31;
            Bs[(r << 5) | (c ^ (r >> 2))] =
                *(const ull*)(B + (size_t)(bn + r) * 256 + kk + c * 2);
        }
        __syncthreads();
#pragma unroll 4
        for (int d2 = 0; d2 < 32; ++d2) {
            ull qv[8], kv[4];
#pragma unroll
            for (int a = 0; a < 8; ++a) qv[a] = As[((qg * 8 + a) << 5) | (d2 ^ qg)];
#pragma unroll
            for (int b = 0; b < 4; ++b) kv[b] = Bs[((kg * 4 + b) << 5) | (d2 ^ kg)];
#pragma unroll
            for (int a = 0; a < 8; ++a)
#pragma unroll
                for (int b = 0; b < 4; ++b) fma2(acc[a][b], qv[a], kv[b]);
        }
    }
    float4 bi = *(const float4*)(bias + bn + kg * 4);
#pragma unroll
    for (int a = 0; a < 8; ++a) {
        int row = bm + qg * 8 + a;
        float2 f0 = unpack2(acc[a][0]);
        float2 f1 = unpack2(acc[a][1]);
        float2 f2 = unpack2(acc[a][2]);
        float2 f3 = unpack2(acc[a][3]);
        float4 o;
        o.x = f0.x + f0.y + bi.x;
        o.y = f1.x + f1.y + bi.y;
        o.z = f2.x + f2.y + bi.z;
        o.w = f3.x + f3.y + bi.w;
        if (ADD_RES) {
            float4 r4 = *(const float4*)(res + (size_t)row * 256 + bn + kg * 4);
            o.x += r4.x; o.y += r4.y; o.z += r4.z; o.w += r4.w;
        }
        *(float4*)(C + (size_t)row * 256 + bn + kg * 4) = o;
    }
}

// ---------------- K1: fused Q/K/V projections ---------------------------------------
__global__ __launch_bounds__(256) void proj_kernel(
    const float* __restrict__ q_in, const float* __restrict__ k_in,
    const float* __restrict__ v_in, const float* __restrict__ Wq,
    const float* __restrict__ bq, const float* __restrict__ Wk,
    const float* __restrict__ bk, const float* __restrict__ Wv,
    const float* __restrict__ bv) {
    const float *A, *B, *bias;
    float* C;
    if (blockIdx.z == 0) { A = q_in; B = Wq; bias = bq; C = g_q; }
    else if (blockIdx.z == 1) { A = k_in; B = Wk; bias = bk; C = g_k; }
    else { A = v_in; B = Wv; bias = bv; C = g_v; }
    gemm128_body<false>(A, B, bias, nullptr, C);
}

// ---------------- K2: fused scores + top-30 + softmax + attn + ctx ------------------
// grid (32 q-tiles, 4 heads), 512 threads: warps 0-7 GEMM, warps 8-15 select.
#define INSERT(rr, cu, ci)                                                          \
    do {                                                                            \
        unsigned m_ =                                                               \
            __ballot_sync(0xFFFFFFFFu,                                              \
                          ((cu) > wu[rr]) || ((cu) == wu[rr] && (ci) < wi[rr]));    \
        while (m_) {                                                                \
            int src_ = __ffs(m_) - 1;                                               \
            m_ &= m_ - 1;                                                           \
            unsigned c2_ = __shfl_sync(0xFFFFFFFFu, (cu), src_);                    \
            int i2_ = __shfl_sync(0xFFFFFFFFu, (ci), src_);                         \
            if ((c2_ > wu[rr]) || (c2_ == wu[rr] && i2_ < wi[rr])) {                \
                if (lane == ws[rr]) { lu[rr] = c2_; li[rr] = i2_; }                 \
                unsigned ku_ = (lane < TOPK) ? lu[rr] : 0xFFFFFFFFu;                \
                wu[rr] = __reduce_min_sync(0xFFFFFFFFu, ku_);                       \
                unsigned wim_ = __reduce_max_sync(                                  \
                    0xFFFFFFFFu, (ku_ == wu[rr]) ? (unsigned)li[rr] : 0u);          \
                wi[rr] = (int)wim_;                                                 \
                unsigned bs_ = __ballot_sync(                                       \
                    0xFFFFFFFFu, ku_ == wu[rr] && (unsigned)li[rr] == wim_);        \
                ws[rr] = __ffs(bs_) - 1;                                            \
            }                                                                       \
        }                                                                           \
    } while (0)

__global__ __launch_bounds__(512, 1) void attn_fused(float* __restrict__ attn) {
    extern __shared__ char smraw[];
    ull* Qs = (ull*)smraw;                  // 128*32 ull = 32KB
    ull* Ks = Qs + 128 * 32;                // 2 * 64*32 ull = 32KB
    float* Sb = (float*)(Ks + 2 * 64 * 32); // 2 * 8192 floats = 64KB
    int* sidx = (int*)Sb;                   // staging (reuses Sb buf0)
    float* sval = ((float*)Sb) + 4096;

    const unsigned FULL = 0xFFFFFFFFu;
    const int tid = threadIdx.x;
    const int wid = tid >> 5, lane = tid & 31;
    const int h = blockIdx.y;
    const int qb0 = blockIdx.x * 128;
    const bool is_compute = wid < 8;

    // load Q tile (all 512 threads)
#pragma unroll
    for (int i = 0; i < 8; ++i) {
        int idx = tid + i * 512;
        int r = idx >> 5, c = idx & 31;
        Qs[(r << 5) | (c ^ (r >> 3))] =
            *(const ull*)(g_q + (size_t)(qb0 + r) * 256 + h * 64 + c * 2);
    }

    // selection state (select warps): distributed top-30 per row, 16 rows/warp
    unsigned lu[16]; int li[16]; unsigned wu[16]; int wi[16]; int ws[16];
    if (!is_compute) {
#pragma unroll
        for (int r = 0; r < 16; ++r) {
            lu[r] = 0u; li[r] = 0x7FFFFFFF;
            wu[r] = 0u; wi[r] = 0x7FFFFFFF; ws[r] = 0;
        }
    }

    const int qg = tid >> 4;  // compute mapping
    const int kg = tid & 15;

    // prologue: K tile 0
    if (is_compute) {
#pragma unroll
        for (int i = 0; i < 8; ++i) {
            int idx = tid + i * 256;
            int r = idx >> 5, c = idx & 31;
            Ks[(r << 5) | (c ^ (r >> 2))] =
                *(const ull*)(g_k + (size_t)r * 256 + h * 64 + c * 2);
        }
    }
    __syncthreads();

    for (int t = 0; t < 64; ++t) {
        if (is_compute) {
            ull kreg[8];
            if (t + 1 < 64) {
#pragma unroll
                for (int i = 0; i < 8; ++i) {
                    int idx = tid + i * 256;
                    int r = idx >> 5, c = idx & 31;
                    kreg[i] = *(const ull*)(g_k + (size_t)((t + 1) * 64 + r) * 256 +
                                            h * 64 + c * 2);
                }
            }
            ull acc[8][4];
#pragma unroll
            for (int a = 0; a < 8; ++a)
#pragma unroll
                for (int b = 0; b < 4; ++b) acc[a][b] = 0ull;
            const ull* Kb = Ks + (t & 1) * (64 * 32);
#pragma unroll 4
            for (int d2 = 0; d2 < 32; ++d2) {
                ull qv[8], kv[4];
#pragma unroll
                for (int a = 0; a < 8; ++a)
                    qv[a] = Qs[((qg * 8 + a) << 5) | (d2 ^ qg)];
#pragma unroll
                for (int b = 0; b < 4; ++b)
                    kv[b] = Kb[((kg * 4 + b) << 5) | (d2 ^ kg)];
#pragma unroll
                for (int a = 0; a < 8; ++a)
#pragma unroll
                    for (int b = 0; b < 4; ++b) fma2(acc[a][b], qv[a], kv[b]);
            }
            float* S = Sb + (t & 1) * 8192;
#pragma unroll
            for (int a = 0; a < 8; ++a) {
                float2 f0 = unpack2(acc[a][0]);
                float2 f1 = unpack2(acc[a][1]);
                float2 f2 = unpack2(acc[a][2]);
                float2 f3 = unpack2(acc[a][3]);
                float4 o;
                o.x = (f0.x + f0.y) * SCALE;
                o.y = (f1.x + f1.y) * SCALE;
                o.z = (f2.x + f2.y) * SCALE;
                o.w = (f3.x + f3.y) * SCALE;
                *(float4*)(S + (qg * 8 + a) * 64 + kg * 4) = o;
            }
            if (t + 1 < 64) {
                ull* Kn = Ks + ((t + 1) & 1) * (64 * 32);
#pragma unroll
                for (int i = 0; i < 8; ++i) {
                    int idx = tid + i * 256;
                    int r = idx >> 5, c = idx & 31;
                    Kn[(r << 5) | (c ^ (r >> 2))] = kreg[i];
                }
            }
        } else if (t >= 1) {
            const float* S = Sb + ((t - 1) & 1) * 8192;
            const int kb = (t - 1) * 64;
#pragma unroll
            for (int rr = 0; rr < 16; ++rr) {
                int row = (wid - 8) * 16 + rr;
                float2 v = *(const float2*)(S + row * 64 + lane * 2);
                {
                    unsigned cu = ford(v.x);
                    int ci = kb + lane * 2;
                    INSERT(rr, cu, ci);
                }
                {
                    unsigned cu = ford(v.y);
                    int ci = kb + lane * 2 + 1;
                    INSERT(rr, cu, ci);
                }
            }
        }
        __syncthreads();
    }
    // final tile (t=63 scores live in buffer 1)
    if (!is_compute) {
        const float* S = Sb + 8192;
        const int kb = 63 * 64;
#pragma unroll
        for (int rr = 0; rr < 16; ++rr) {
            int row = (wid - 8) * 16 + rr;
            float2 v = *(const float2*)(S + row * 64 + lane * 2);
            {
                unsigned cu = ford(v.x);
                int ci = kb + lane * 2;
                INSERT(rr, cu, ci);
            }
            {
                unsigned cu = ford(v.y);
                int ci = kb + lane * 2 + 1;
                INSERT(rr, cu, ci);
            }
        }
    }
    __syncthreads();

    // softmax per row -> staging (select warps)
    if (!is_compute) {
#pragma unroll
        for (int rr = 0; rr < 16; ++rr) {
            int row = (wid - 8) * 16 + rr;
            unsigned mx = __reduce_max_sync(FULL, (lane < TOPK) ? lu[rr] : 0u);
            float mval = unford(mx);
            float lv = (lane < TOPK) ? unford(lu[rr]) : -CUDART_INF_F;
            float e = (lane < TOPK) ? expf(lv - mval) : 0.f;
            float s = e;
#pragma unroll
            for (int o = 16; o; o >>= 1) s += __shfl_xor_sync(FULL, s, o);
            float p = e / s;
            sidx[row * 32 + lane] = li[rr];
            sval[row * 32 + lane] = (lane < TOPK) ? p : 0.f;
        }
    }
    __syncthreads();

    // zero this block's 128 attn rows (2 MB)
    float* arow0 = attn + (size_t)(h * N_TOK + qb0) * N_TOK;
    float4* a4 = (float4*)arow0;
    const float4 z4 = make_float4(0.f, 0.f, 0.f, 0.f);
#pragma unroll 8
    for (int i = tid; i < 128 * (N_TOK / 4); i += 512) a4[i] = z4;
    __syncthreads();

    // scatter + sparse ctx: each of 16 warps owns 8 rows
#pragma unroll
    for (int rr = 0; rr < 8; ++rr) {
        int row = wid * 8 + rr;
        float p = sval[row * 32 + lane];
        int idx = sidx[row * 32 + lane];
        if (lane < TOPK) arow0[(size_t)row * N_TOK + idx] = p;
        float2 acc = make_float2(0.f, 0.f);
        const float* vb = g_v + h * 64 + 2 * lane;
#pragma unroll 6
        for (int j = 0; j < TOPK; ++j) {
            float pj = sval[row * 32 + j];
            int ij = sidx[row * 32 + j];
            float2 vv = *(const float2*)(vb + (size_t)ij * 256);
            acc.x += pj * vv.x;
            acc.y += pj * vv.y;
        }
        *(float2*)(g_ctx + (size_t)(qb0 + row) * 256 + h * 64 + 2 * lane) = acc;
    }
}

// ---------------- K3: out-proj + residual -> g_resid --------------------------------
__global__ __launch_bounds__(256) void oproj_kernel(const float* __restrict__ Wo,
                                                    const float* __restrict__ bo,
                                                    const float* __restrict__ q_in) {
    gemm128_body<true>(g_ctx, Wo, bo, q_in, g_resid);
}

// ---------------- K4: row LayerNorm -> d_out[0 : N*D] -------------------------------
__global__ __launch_bounds__(256) void ln_kernel(const float* __restrict__ g,
                                                 const float* __restrict__ b,
                                                 float* __restrict__ out) {
    const int row = blockIdx.x;
    const int tid = threadIdx.x;
    float x = g_resid[(size_t)row * 256 + tid];
    float s = x, s2 = x * x;
#pragma unroll
    for (int o = 16; o; o >>= 1) {
        s += __shfl_xor_sync(0xFFFFFFFFu, s, o);
        s2 += __shfl_xor_sync(0xFFFFFFFFu, s2, o);
    }
    __shared__ float rs[8], rs2[8];
    const int w = tid >> 5, lane = tid & 31;
    if (lane == 0) { rs[w] = s; rs2[w] = s2; }
    __syncthreads();
    float tot = 0.f, tot2 = 0.f;
#pragma unroll
    for (int i = 0; i < 8; ++i) { tot += rs[i]; tot2 += rs2[i]; }
    float mu = tot * (1.0f / 256.0f);
    float var = tot2 * (1.0f / 256.0f) - mu * mu;
    float inv = rsqrtf(var + LN_EPS);
    out[(size_t)row * 256 + tid] = (x - mu) * inv * g[tid] + b[tid];
}

// ---------------- launch --------------------------------------------------------------
extern "C" void kernel_launch(void* const* d_in, const int* in_sizes, int n_in,
                              void* d_out, int out_size) {
    const float* key_in   = (const float*)d_in[0];
    const float* value_in = (const float*)d_in[1];
    const float* query_in = (const float*)d_in[2];
    const float* Wq = (const float*)d_in[3];
    const float* bq = (const float*)d_in[4];
    const float* Wk = (const float*)d_in[5];
    const float* bk = (const float*)d_in[6];
    const float* Wv = (const float*)d_in[7];
    const float* bv = (const float*)d_in[8];
    const float* Wo = (const float*)d_in[9];
    const float* bo = (const float*)d_in[10];
    const float* ln_g = (const float*)d_in[11];
    const float* ln_b = (const float*)d_in[12];

    float* out = (float*)d_out;
    float* attn = out + (size_t)N_TOK * DMODEL;

    const int FUSED_SMEM = 128 * 32 * 8 + 2 * 64 * 32 * 8 + 2 * 8192 * 4;  // 128KB
    cudaFuncSetAttribute(attn_fused, cudaFuncAttributeMaxDynamicSharedMemorySize,
                         FUSED_SMEM);

    // 1) Q/K/V projections
    proj_kernel<<<dim3(4, 32, 3), 256>>>(query_in, key_in, value_in, Wq, bq, Wk, bk,
                                         Wv, bv);
    // 2) fused scores + top-30 + softmax + attn write + sparse ctx
    attn_fused<<<dim3(32, 4), 512, FUSED_SMEM>>>(attn);
    // 3) output projection + residual
    oproj_kernel<<<dim3(4, 32), 256>>>(Wo, bo, query_in);
    // 4) layernorm
    ln_kernel<<<N_TOK, 256>>>(ln_g, ln_b, out);
}